// round 5
// baseline (speedup 1.0000x reference)
#include <cuda_runtime.h>
#include <cuda_fp16.h>
#include <cstdint>

// ---------------- problem constants ----------------
constexpr int B    = 2;
constexpr int N    = 6400;
constexpr int E    = 256;
constexpr int CAMS = 6;
constexpr int LVLS = 4;
constexpr int BN_PTS = B * N;          // 12800
__device__ constexpr int HGT[LVLS]  = {64, 32, 16, 8};
__device__ constexpr int WID[LVLS]  = {176, 88, 44, 22};
__device__ constexpr int LOFF[LVLS] = {0, 11264, 14080, 14784};
constexpr int TOTHW = 14960;           // sum of H*W

// ---------------- device scratch (no runtime alloc allowed) ----------------
__device__ __half g_featT[(size_t)B * CAMS * TOTHW * E];  // ~92 MB, [b,c,hw,E] fp16
__device__ float g_attn[BN_PTS * CAMS * LVLS];            // softmaxed weights
__device__ float g_uv[BN_PTS * CAMS * 2];                 // pixel coords
__device__ float g_agg[(size_t)BN_PTS * E];               // aggregation result
__device__ float g_wcat[256 * 512];                       // [Wc | op_w], row-major n x 512
__device__ float g_bc[256];                               // combined bias

// ---------------- 1) feature transpose: [b,c,E,H,W] -> [b,c,HW,E] fp16 -----
template <int L>
__global__ __launch_bounds__(256) void transpose_kernel(const float* __restrict__ src0) {
    constexpr int H  = (L == 0 ? 64 : L == 1 ? 32 : L == 2 ? 16 : 8);
    constexpr int W  = (L == 0 ? 176 : L == 1 ? 88 : L == 2 ? 44 : 22);
    constexpr int HW = H * W;
    constexpr int OFF = (L == 0 ? 0 : L == 1 ? 11264 : L == 2 ? 14080 : 14784);

    int bc  = blockIdx.z;                 // 0..11
    int hw0 = blockIdx.x * 32;
    int e0  = blockIdx.y * 32;

    const float* src = src0 + (size_t)bc * E * HW;
    __half* dst = g_featT + ((size_t)bc * TOTHW + OFF) * E;

    __shared__ float tile[32][33];        // [e][hw]
    int tx = threadIdx.x, ty = threadIdx.y;   // (32,8)
    #pragma unroll
    for (int i = 0; i < 4; i++) {
        int e  = e0 + ty + i * 8;
        int hw = hw0 + tx;
        tile[ty + i * 8][tx] = (hw < HW) ? src[(size_t)e * HW + hw] : 0.0f;
    }
    __syncthreads();
    // write: 256 threads cover 32 hw-rows x 16 half2-cols, 2 rows per thread
    int t    = ty * 32 + tx;
    int col  = t & 15;                    // half2 column (2 e values)
    int row0 = t >> 4;                    // 0..15
    #pragma unroll
    for (int i = 0; i < 2; i++) {
        int row = row0 + i * 16;
        int hw  = hw0 + row;
        if (hw < HW) {
            __half2 v = __floats2half2_rn(tile[col * 2][row], tile[col * 2 + 1][row]);
            *(__half2*)(dst + (size_t)hw * E + e0 + col * 2) = v;
        }
    }
}

// ---------------- 2) prep: attn softmax + uv projection --------------------
__global__ __launch_bounds__(256) void prep_kernel(
                            const float* __restrict__ instf,
                            const float* __restrict__ anchor,
                            const float* __restrict__ proj,
                            const float* __restrict__ attn_w,
                            const float* __restrict__ attn_b) {
    int warp = (blockIdx.x * blockDim.x + threadIdx.x) >> 5;
    int lane = threadIdx.x & 31;
    if (warp >= BN_PTS) return;
    int p = warp;
    int b = p / N;

    const float* ifp = instf + (size_t)p * E;
    float v[8];
    #pragma unroll
    for (int k = 0; k < 8; k++) v[k] = ifp[k * 32 + lane];

    float logit[24];
    #pragma unroll
    for (int cl = 0; cl < 24; cl++) {
        const float* w = attn_w + cl * E;
        float s = 0.f;
        #pragma unroll
        for (int k = 0; k < 8; k++) s = fmaf(v[k], w[k * 32 + lane], s);
        #pragma unroll
        for (int o = 16; o; o >>= 1) s += __shfl_xor_sync(0xffffffffu, s, o);
        logit[cl] = s + attn_b[cl];
    }

    if (lane == 0) {
        #pragma unroll
        for (int c = 0; c < CAMS; c++) {
            float l0 = logit[c * 4 + 0], l1 = logit[c * 4 + 1];
            float l2 = logit[c * 4 + 2], l3 = logit[c * 4 + 3];
            float mx = fmaxf(fmaxf(l0, l1), fmaxf(l2, l3));
            float e0 = expf(l0 - mx), e1 = expf(l1 - mx);
            float e2 = expf(l2 - mx), e3 = expf(l3 - mx);
            float inv = 1.0f / (e0 + e1 + e2 + e3);
            float* ap = g_attn + (size_t)p * 24 + c * 4;
            ap[0] = e0 * inv; ap[1] = e1 * inv; ap[2] = e2 * inv; ap[3] = e3 * inv;
        }
    }

    float ax = anchor[(size_t)p * 11 + 0];
    float ay = anchor[(size_t)p * 11 + 1];
    float az = anchor[(size_t)p * 11 + 2];
    float sx = 1.0f / (1.0f + expf(-ax));
    float sy = 1.0f / (1.0f + expf(-ay));
    float sz = 1.0f / (1.0f + expf(-az));
    float X = sx * 102.4f - 51.2f;
    float Y = sy * 102.4f - 51.2f;
    float Z = sz * 8.0f   - 5.0f;

    if (lane < CAMS) {
        const float* P = proj + ((size_t)b * CAMS + lane) * 16;
        float c0 = P[0]  * X + P[1]  * Y + P[2]  * Z + P[3];
        float c1 = P[4]  * X + P[5]  * Y + P[6]  * Z + P[7];
        float c2 = P[8]  * X + P[9]  * Y + P[10] * Z + P[11];
        float d  = fmaxf(c2, 0.0001f);
        g_uv[(size_t)p * 12 + lane * 2 + 0] = c0 / d;
        g_uv[(size_t)p * 12 + lane * 2 + 1] = c1 / d;
    }
}

// ---------------- 3) bilinear gather + weighted aggregation (fp16 feats) ---
// 8 points per block; 32 threads per point; each thread owns 8 channels.
__global__ __launch_bounds__(256) void aggregate_kernel() {
    int t    = threadIdx.x;
    int pt   = t >> 5;                // 0..7 point-within-block
    int lane = t & 31;                // channel group of 8
    int p    = blockIdx.x * 8 + pt;
    int b    = p / N;

    __shared__ float s_attn[8][24];
    __shared__ float s_uv[8][12];
    if (lane < 24) s_attn[pt][lane] = g_attn[(size_t)p * 24 + lane];
    if (lane < 12) s_uv[pt][lane]   = g_uv[(size_t)p * 12 + lane];
    __syncthreads();

    float acc[8] = {0.f, 0.f, 0.f, 0.f, 0.f, 0.f, 0.f, 0.f};

    #pragma unroll
    for (int c = 0; c < CAMS; c++) {
        float x = s_uv[pt][c * 2 + 0];
        float y = s_uv[pt][c * 2 + 1];
        float x0 = floorf(x), y0 = floorf(y);
        float wx1 = x - x0, wx0 = 1.0f - wx1;
        float wy1 = y - y0, wy0 = 1.0f - wy1;
        const __half* base = g_featT + ((size_t)b * CAMS + c) * TOTHW * E;
        #pragma unroll
        for (int l = 0; l < LVLS; l++) {
            const int Wl = WID[l], Hl = HGT[l], off = LOFF[l];
            float wa = s_attn[pt][c * 4 + l];
            #pragma unroll
            for (int cy = 0; cy < 2; cy++) {
                float yf = y0 + cy;
                float wy = cy ? wy1 : wy0;
                if (yf < 0.f || yf > (float)(Hl - 1)) continue;
                #pragma unroll
                for (int cx = 0; cx < 2; cx++) {
                    float xf = x0 + cx;
                    float wx = cx ? wx1 : wx0;
                    if (xf < 0.f || xf > (float)(Wl - 1)) continue;
                    float wgt = wa * wx * wy;
                    int xi = (int)xf, yi = (int)yf;
                    const __half* fp = base + ((size_t)(off + yi * Wl + xi)) * E + lane * 8;
                    uint4 raw = *(const uint4*)fp;
                    const __half2* h2 = (const __half2*)&raw;
                    #pragma unroll
                    for (int q = 0; q < 4; q++) {
                        float2 f = __half22float2(h2[q]);
                        acc[q * 2 + 0] = fmaf(wgt, f.x, acc[q * 2 + 0]);
                        acc[q * 2 + 1] = fmaf(wgt, f.y, acc[q * 2 + 1]);
                    }
                }
            }
        }
    }
    float* op = g_agg + (size_t)p * E + lane * 8;
    *(float4*)op       = make_float4(acc[0], acc[1], acc[2], acc[3]);
    *(float4*)(op + 4) = make_float4(acc[4], acc[5], acc[6], acc[7]);
}

// ---------------- 4a) weight fold: Wcat = [op_w @ vp_w | op_w], bc ---------
// grid (4,4), block 256; block computes 64x64 tile of Wc (NN gemm) and copies
// the matching op_w tile into the right half of Wcat.
__global__ __launch_bounds__(256) void weight_fold_kernel(
        const float* __restrict__ op_w,   // [256,256] row-major
        const float* __restrict__ vp_w) { // [256,256] row-major
    __shared__ float sA[16][68];   // [i][n]
    __shared__ float sB[16][68];   // [i][k]

    int n0 = blockIdx.x * 64;
    int k0 = blockIdx.y * 64;
    int t  = threadIdx.x;
    int tx = t & 15, ty = t >> 4;

    float acc[4][4] = {};

    for (int i0 = 0; i0 < 256; i0 += 16) {
        // load op tile: 64 n x 16 i  (float4 along i)
        {
            int nrow = t >> 2;        // 0..63
            int iq   = t & 3;
            float4 a = *(const float4*)(op_w + (size_t)(n0 + nrow) * 256 + i0 + iq * 4);
            sA[iq * 4 + 0][nrow] = a.x;
            sA[iq * 4 + 1][nrow] = a.y;
            sA[iq * 4 + 2][nrow] = a.z;
            sA[iq * 4 + 3][nrow] = a.w;
        }
        // load vp tile: 16 i x 64 k (float4 along k)
        {
            int irow = t >> 4;        // 0..15
            int kq   = t & 15;
            float4 bv = *(const float4*)(vp_w + (size_t)(i0 + irow) * 256 + k0 + kq * 4);
            sB[irow][kq * 4 + 0] = bv.x;
            sB[irow][kq * 4 + 1] = bv.y;
            sB[irow][kq * 4 + 2] = bv.z;
            sB[irow][kq * 4 + 3] = bv.w;
        }
        __syncthreads();
        #pragma unroll
        for (int i = 0; i < 16; i++) {
            float ra[4], rb[4];
            #pragma unroll
            for (int u = 0; u < 4; u++) ra[u] = sA[i][ty * 4 + u];
            #pragma unroll
            for (int v = 0; v < 4; v++) rb[v] = sB[i][tx * 4 + v];
            #pragma unroll
            for (int u = 0; u < 4; u++)
                #pragma unroll
                for (int v = 0; v < 4; v++)
                    acc[u][v] = fmaf(ra[u], rb[v], acc[u][v]);
        }
        __syncthreads();
    }

    #pragma unroll
    for (int u = 0; u < 4; u++)
        #pragma unroll
        for (int v = 0; v < 4; v++)
            g_wcat[(size_t)(n0 + ty * 4 + u) * 512 + k0 + tx * 4 + v] = acc[u][v];

    // copy op_w tile into cols [256,512)
    #pragma unroll
    for (int r = 0; r < 4; r++) {
        int row  = r * 16 + (t >> 4);
        int col4 = t & 15;
        float4 w = *(const float4*)(op_w + (size_t)(n0 + row) * 256 + k0 + col4 * 4);
        *(float4*)(g_wcat + (size_t)(n0 + row) * 512 + 256 + k0 + col4 * 4) = w;
    }
}

__global__ __launch_bounds__(256) void bias_fold_kernel(
        const float* __restrict__ op_w,
        const float* __restrict__ vp_b,
        const float* __restrict__ op_b) {
    int n = threadIdx.x;              // 256 threads, 1 block
    float s = op_b[n];
    const float* row = op_w + (size_t)n * 256;
    #pragma unroll 8
    for (int i = 0; i < 256; i++) s = fmaf(row[i], vp_b[i], s);
    g_bc[n] = s;
}

// ---------------- 4b) merged GEMM: out = [agg|instf] @ Wcat^T + bc ---------
// BM=128, BN=128, BK=16, K=512, 256 threads, 8x8 microtile, double buffered.
constexpr int GBM = 128, GBN = 128, GBK = 16, GK = 512;
__global__ __launch_bounds__(256) void gemm_merged_kernel(
        const float* __restrict__ instf,
        float* __restrict__ Cout) {
    __shared__ float sA[2][GBK][GBM + 4];
    __shared__ float sB[2][GBK][GBN + 4];

    int bm = blockIdx.x * GBM;
    int bn = blockIdx.y * GBN;
    int t  = threadIdx.x;
    int tx = t & 15;                   // col groups
    int ty = t >> 4;                   // row groups

    int arow = t >> 2;                 // 0..63 (+64 second)
    int akq  = t & 3;

    float4 pa0, pa1, pb0, pb1;
    auto load_tile = [&](int k0) {
        const float* Asrc; int kk;
        if (k0 < 256) { Asrc = g_agg;  kk = k0; }
        else          { Asrc = instf;  kk = k0 - 256; }
        pa0 = *(const float4*)(Asrc + (size_t)(bm + arow) * 256 + kk + akq * 4);
        pa1 = *(const float4*)(Asrc + (size_t)(bm + arow + 64) * 256 + kk + akq * 4);
        pb0 = *(const float4*)(g_wcat + (size_t)(bn + arow) * 512 + k0 + akq * 4);
        pb1 = *(const float4*)(g_wcat + (size_t)(bn + arow + 64) * 512 + k0 + akq * 4);
    };
    auto store_tile = [&](int buf) {
        #pragma unroll
        for (int q = 0; q < 4; q++) {
            sA[buf][akq * 4 + q][arow]      = ((const float*)&pa0)[q];
            sA[buf][akq * 4 + q][arow + 64] = ((const float*)&pa1)[q];
            sB[buf][akq * 4 + q][arow]      = ((const float*)&pb0)[q];
            sB[buf][akq * 4 + q][arow + 64] = ((const float*)&pb1)[q];
        }
    };

    float acc[8][8];
    #pragma unroll
    for (int i = 0; i < 8; i++)
        #pragma unroll
        for (int j = 0; j < 8; j++) acc[i][j] = 0.f;

    load_tile(0);
    store_tile(0);
    __syncthreads();

    const int NT = GK / GBK;           // 32
    #pragma unroll 1
    for (int kt = 0; kt < NT; kt++) {
        int buf = kt & 1;
        if (kt + 1 < NT) load_tile((kt + 1) * GBK);

        #pragma unroll
        for (int k = 0; k < GBK; k++) {
            float ra[8], rb[8];
            #pragma unroll
            for (int u = 0; u < 4; u++) {
                ra[u]     = sA[buf][k][ty * 4 + u];
                ra[4 + u] = sA[buf][k][64 + ty * 4 + u];
                rb[u]     = sB[buf][k][tx * 4 + u];
                rb[4 + u] = sB[buf][k][64 + tx * 4 + u];
            }
            #pragma unroll
            for (int i = 0; i < 8; i++)
                #pragma unroll
                for (int j = 0; j < 8; j++)
                    acc[i][j] = fmaf(ra[i], rb[j], acc[i][j]);
        }

        if (kt + 1 < NT) {
            store_tile(1 - buf);
            __syncthreads();
        }
    }

    // epilogue: bias + float4 stores
    float4 bv0 = *(const float4*)(g_bc + bn + tx * 4);
    float4 bv1 = *(const float4*)(g_bc + bn + 64 + tx * 4);
    #pragma unroll
    for (int i = 0; i < 8; i++) {
        int row = (i < 4) ? (ty * 4 + i) : (64 + ty * 4 + (i - 4));
        float* crow = Cout + (size_t)(bm + row) * 256;
        float4 o0, o1;
        o0.x = acc[i][0] + bv0.x; o0.y = acc[i][1] + bv0.y;
        o0.z = acc[i][2] + bv0.z; o0.w = acc[i][3] + bv0.w;
        o1.x = acc[i][4] + bv1.x; o1.y = acc[i][5] + bv1.y;
        o1.z = acc[i][6] + bv1.z; o1.w = acc[i][7] + bv1.w;
        *(float4*)(crow + bn + tx * 4)      = o0;
        *(float4*)(crow + bn + 64 + tx * 4) = o1;
    }
}

// ---------------- launch ----------------
extern "C" void kernel_launch(void* const* d_in, const int* in_sizes, int n_in,
                              void* d_out, int out_size) {
    const float* instf  = (const float*)d_in[0];
    const float* anchor = (const float*)d_in[1];
    const float* proj   = (const float*)d_in[2];
    const float* f0     = (const float*)d_in[3];
    const float* f1     = (const float*)d_in[4];
    const float* f2     = (const float*)d_in[5];
    const float* f3     = (const float*)d_in[6];
    const float* attn_w = (const float*)d_in[7];
    const float* attn_b = (const float*)d_in[8];
    const float* vp_w   = (const float*)d_in[9];
    const float* vp_b   = (const float*)d_in[10];
    const float* op_w   = (const float*)d_in[11];
    const float* op_b   = (const float*)d_in[12];
    float* out = (float*)d_out;

    // weight folding (independent of everything else)
    weight_fold_kernel<<<dim3(4, 4), 256>>>(op_w, vp_w);
    bias_fold_kernel<<<1, 256>>>(op_w, vp_b, op_b);

    // 1) transpose features to channel-last fp16 (exact grid per level)
    dim3 tb(32, 8);
    transpose_kernel<0><<<dim3(352, 8, B * CAMS), tb>>>(f0);   // 64x176
    transpose_kernel<1><<<dim3(88,  8, B * CAMS), tb>>>(f1);   // 32x88
    transpose_kernel<2><<<dim3(22,  8, B * CAMS), tb>>>(f2);   // 16x44
    transpose_kernel<3><<<dim3(6,   8, B * CAMS), tb>>>(f3);   // 8x22

    // 2) attn softmax + uv
    prep_kernel<<<(BN_PTS * 32 + 255) / 256, 256>>>(instf, anchor, proj, attn_w, attn_b);

    // 3) aggregate (8 points / block)
    aggregate_kernel<<<BN_PTS / 8, 256>>>();

    // 4) single merged GEMM
    dim3 gg(BN_PTS / GBM, 256 / GBN);
    gemm_merged_kernel<<<gg, 256>>>(instf, out);
}

// round 6
// speedup vs baseline: 1.2357x; 1.2357x over previous
#include <cuda_runtime.h>
#include <cuda_fp16.h>
#include <cstdint>

// ---------------- problem constants ----------------
constexpr int B    = 2;
constexpr int N    = 6400;
constexpr int E    = 256;
constexpr int CAMS = 6;
constexpr int LVLS = 4;
constexpr int BN_PTS = B * N;          // 12800
__device__ constexpr int HGT[LVLS]  = {64, 32, 16, 8};
__device__ constexpr int WID[LVLS]  = {176, 88, 44, 22};
__device__ constexpr int LOFF[LVLS] = {0, 11264, 14080, 14784};
constexpr int TOTHW = 14960;           // sum of H*W

// ---------------- device scratch (no runtime alloc allowed) ----------------
__device__ __half g_featT[(size_t)B * CAMS * TOTHW * E];  // ~92 MB, [b,c,hw,E] fp16
__device__ float g_attn[BN_PTS * CAMS * LVLS];            // softmaxed weights
__device__ float g_uv[BN_PTS * CAMS * 2];                 // pixel coords
__device__ float g_agg[(size_t)BN_PTS * E];               // aggregation result
__device__ float g_tmp[(size_t)BN_PTS * E];               // after vp GEMM

// ---------------- 1) feature transpose: [b,c,E,H,W] -> [b,c,HW,E] fp16 -----
template <int L>
__global__ __launch_bounds__(256) void transpose_kernel(const float* __restrict__ src0) {
    constexpr int H  = (L == 0 ? 64 : L == 1 ? 32 : L == 2 ? 16 : 8);
    constexpr int W  = (L == 0 ? 176 : L == 1 ? 88 : L == 2 ? 44 : 22);
    constexpr int HW = H * W;
    constexpr int OFF = (L == 0 ? 0 : L == 1 ? 11264 : L == 2 ? 14080 : 14784);

    int bc  = blockIdx.z;                 // 0..11
    int hw0 = blockIdx.x * 32;
    int e0  = blockIdx.y * 32;

    const float* src = src0 + (size_t)bc * E * HW;
    __half* dst = g_featT + ((size_t)bc * TOTHW + OFF) * E;

    __shared__ float tile[32][33];        // [e][hw]
    int tx = threadIdx.x, ty = threadIdx.y;   // (32,8)
    #pragma unroll
    for (int i = 0; i < 4; i++) {
        int e  = e0 + ty + i * 8;
        int hw = hw0 + tx;
        tile[ty + i * 8][tx] = (hw < HW) ? src[(size_t)e * HW + hw] : 0.0f;
    }
    __syncthreads();
    // write: 256 threads = 32 hw-rows x 8 segs; each thread stores 4 halves (8B)
    int t   = ty * 32 + tx;
    int row = t >> 3;                     // hw row 0..31
    int seg = t & 7;                      // e segment of 4
    int hw  = hw0 + row;
    if (hw < HW) {
        __half2 v0 = __floats2half2_rn(tile[seg * 4 + 0][row], tile[seg * 4 + 1][row]);
        __half2 v1 = __floats2half2_rn(tile[seg * 4 + 2][row], tile[seg * 4 + 3][row]);
        uint2 pk;
        pk.x = *(const unsigned*)&v0;
        pk.y = *(const unsigned*)&v1;
        *(uint2*)(dst + (size_t)hw * E + e0 + seg * 4) = pk;
    }
}

// ---------------- 2) prep: attn softmax + uv projection --------------------
__global__ __launch_bounds__(256) void prep_kernel(
                            const float* __restrict__ instf,
                            const float* __restrict__ anchor,
                            const float* __restrict__ proj,
                            const float* __restrict__ attn_w,
                            const float* __restrict__ attn_b) {
    int warp = (blockIdx.x * blockDim.x + threadIdx.x) >> 5;
    int lane = threadIdx.x & 31;
    if (warp >= BN_PTS) return;
    int p = warp;
    int b = p / N;

    const float* ifp = instf + (size_t)p * E;
    float v[8];
    #pragma unroll
    for (int k = 0; k < 8; k++) v[k] = ifp[k * 32 + lane];

    float logit[24];
    #pragma unroll
    for (int cl = 0; cl < 24; cl++) {
        const float* w = attn_w + cl * E;
        float s = 0.f;
        #pragma unroll
        for (int k = 0; k < 8; k++) s = fmaf(v[k], w[k * 32 + lane], s);
        #pragma unroll
        for (int o = 16; o; o >>= 1) s += __shfl_xor_sync(0xffffffffu, s, o);
        logit[cl] = s + attn_b[cl];
    }

    if (lane == 0) {
        #pragma unroll
        for (int c = 0; c < CAMS; c++) {
            float l0 = logit[c * 4 + 0], l1 = logit[c * 4 + 1];
            float l2 = logit[c * 4 + 2], l3 = logit[c * 4 + 3];
            float mx = fmaxf(fmaxf(l0, l1), fmaxf(l2, l3));
            float e0 = expf(l0 - mx), e1 = expf(l1 - mx);
            float e2 = expf(l2 - mx), e3 = expf(l3 - mx);
            float inv = 1.0f / (e0 + e1 + e2 + e3);
            float* ap = g_attn + (size_t)p * 24 + c * 4;
            ap[0] = e0 * inv; ap[1] = e1 * inv; ap[2] = e2 * inv; ap[3] = e3 * inv;
        }
    }

    float ax = anchor[(size_t)p * 11 + 0];
    float ay = anchor[(size_t)p * 11 + 1];
    float az = anchor[(size_t)p * 11 + 2];
    float sx = 1.0f / (1.0f + expf(-ax));
    float sy = 1.0f / (1.0f + expf(-ay));
    float sz = 1.0f / (1.0f + expf(-az));
    float X = sx * 102.4f - 51.2f;
    float Y = sy * 102.4f - 51.2f;
    float Z = sz * 8.0f   - 5.0f;

    if (lane < CAMS) {
        const float* P = proj + ((size_t)b * CAMS + lane) * 16;
        float c0 = P[0]  * X + P[1]  * Y + P[2]  * Z + P[3];
        float c1 = P[4]  * X + P[5]  * Y + P[6]  * Z + P[7];
        float c2 = P[8]  * X + P[9]  * Y + P[10] * Z + P[11];
        float d  = fmaxf(c2, 0.0001f);
        g_uv[(size_t)p * 12 + lane * 2 + 0] = c0 / d;
        g_uv[(size_t)p * 12 + lane * 2 + 1] = c1 / d;
    }
}

// ---------------- 3) bilinear gather + weighted aggregation (fp16 feats) ---
// 8 points per block; 32 threads per point; each thread owns 8 channels.
__global__ __launch_bounds__(256) void aggregate_kernel() {
    int t    = threadIdx.x;
    int pt   = t >> 5;                // 0..7 point-within-block
    int lane = t & 31;                // channel group of 8
    int p    = blockIdx.x * 8 + pt;
    int b    = p / N;

    __shared__ float s_attn[8][24];
    __shared__ float s_uv[8][12];
    if (lane < 24) s_attn[pt][lane] = g_attn[(size_t)p * 24 + lane];
    if (lane < 12) s_uv[pt][lane]   = g_uv[(size_t)p * 12 + lane];
    __syncthreads();

    float acc[8] = {0.f, 0.f, 0.f, 0.f, 0.f, 0.f, 0.f, 0.f};

    #pragma unroll
    for (int c = 0; c < CAMS; c++) {
        float x = s_uv[pt][c * 2 + 0];
        float y = s_uv[pt][c * 2 + 1];
        float x0 = floorf(x), y0 = floorf(y);
        float wx1 = x - x0, wx0 = 1.0f - wx1;
        float wy1 = y - y0, wy0 = 1.0f - wy1;
        const __half* base = g_featT + ((size_t)b * CAMS + c) * TOTHW * E;
        #pragma unroll
        for (int l = 0; l < LVLS; l++) {
            const int Wl = WID[l], Hl = HGT[l], off = LOFF[l];
            float wa = s_attn[pt][c * 4 + l];
            #pragma unroll
            for (int cy = 0; cy < 2; cy++) {
                float yf = y0 + cy;
                float wy = cy ? wy1 : wy0;
                if (yf < 0.f || yf > (float)(Hl - 1)) continue;
                #pragma unroll
                for (int cx = 0; cx < 2; cx++) {
                    float xf = x0 + cx;
                    float wx = cx ? wx1 : wx0;
                    if (xf < 0.f || xf > (float)(Wl - 1)) continue;
                    float wgt = wa * wx * wy;
                    int xi = (int)xf, yi = (int)yf;
                    const __half* fp = base + ((size_t)(off + yi * Wl + xi)) * E + lane * 8;
                    uint4 raw = *(const uint4*)fp;
                    const __half2* h2 = (const __half2*)&raw;
                    #pragma unroll
                    for (int q = 0; q < 4; q++) {
                        float2 f = __half22float2(h2[q]);
                        acc[q * 2 + 0] = fmaf(wgt, f.x, acc[q * 2 + 0]);
                        acc[q * 2 + 1] = fmaf(wgt, f.y, acc[q * 2 + 1]);
                    }
                }
            }
        }
    }
    float* op = g_agg + (size_t)p * E + lane * 8;
    *(float4*)op       = make_float4(acc[0], acc[1], acc[2], acc[3]);
    *(float4*)(op + 4) = make_float4(acc[4], acc[5], acc[6], acc[7]);
}

// ---------------- 4) fused NT-GEMM:  C = (A [+Aadd]) @ W^T + bias ----------
// A: [M,256] row-major, W: [256,256] row-major, C: [M,256]
// BM=128, BN=64, BK=16, 256 threads, microtile 8x4 (rows split 4+4).
constexpr int GBM = 128, GBN = 64, GBK = 16;
__global__ __launch_bounds__(256) void gemm_nt_kernel(int mode,
                               const float* __restrict__ Wm,
                               const float* __restrict__ bias,
                               const float* __restrict__ Aadd,
                               float* __restrict__ Cout) {
    const int K = 256;
    const float* A = (mode == 0) ? g_agg : g_tmp;
    float* C       = (mode == 0) ? g_tmp : Cout;

    __shared__ float sA[2][GBK][GBM + 4];
    __shared__ float sB[2][GBK][GBN + 4];

    int bm = blockIdx.x * GBM;
    int bn = blockIdx.y * GBN;
    int t  = threadIdx.x;              // 256 threads
    int tx = t & 15;                   // 16 cols of 4
    int ty = t >> 4;                   // 16 row-groups of (4 + 4 split)

    int arow0 = t >> 2;                // 0..63   (two iters: +64)
    int akq   = t & 3;                 // k-quarter
    int brow  = t >> 2;                // 0..63
    int bkq   = t & 3;

    float4 pa0, pa1, pb;
    auto load_tile = [&](int k0) {
        pa0 = *(const float4*)(A + (size_t)(bm + arow0) * K + k0 + akq * 4);
        pa1 = *(const float4*)(A + (size_t)(bm + arow0 + 64) * K + k0 + akq * 4);
        if (mode == 1) {
            float4 r0 = *(const float4*)(Aadd + (size_t)(bm + arow0) * K + k0 + akq * 4);
            float4 r1 = *(const float4*)(Aadd + (size_t)(bm + arow0 + 64) * K + k0 + akq * 4);
            pa0.x += r0.x; pa0.y += r0.y; pa0.z += r0.z; pa0.w += r0.w;
            pa1.x += r1.x; pa1.y += r1.y; pa1.z += r1.z; pa1.w += r1.w;
        }
        pb = *(const float4*)(Wm + (size_t)(bn + brow) * K + k0 + bkq * 4);
    };
    auto store_tile = [&](int buf) {
        sA[buf][akq * 4 + 0][arow0] = pa0.x;
        sA[buf][akq * 4 + 1][arow0] = pa0.y;
        sA[buf][akq * 4 + 2][arow0] = pa0.z;
        sA[buf][akq * 4 + 3][arow0] = pa0.w;
        sA[buf][akq * 4 + 0][arow0 + 64] = pa1.x;
        sA[buf][akq * 4 + 1][arow0 + 64] = pa1.y;
        sA[buf][akq * 4 + 2][arow0 + 64] = pa1.z;
        sA[buf][akq * 4 + 3][arow0 + 64] = pa1.w;
        sB[buf][bkq * 4 + 0][brow] = pb.x;
        sB[buf][bkq * 4 + 1][brow] = pb.y;
        sB[buf][bkq * 4 + 2][brow] = pb.z;
        sB[buf][bkq * 4 + 3][brow] = pb.w;
    };

    float acc[8][4];
    #pragma unroll
    for (int i = 0; i < 8; i++)
        #pragma unroll
        for (int j = 0; j < 4; j++) acc[i][j] = 0.f;

    load_tile(0);
    store_tile(0);
    __syncthreads();

    const int NT = K / GBK;            // 16
    #pragma unroll 1
    for (int kt = 0; kt < NT; kt++) {
        int buf = kt & 1;
        if (kt + 1 < NT) load_tile((kt + 1) * GBK);

        #pragma unroll
        for (int k = 0; k < GBK; k++) {
            float ra[8], rb[4];
            #pragma unroll
            for (int i = 0; i < 4; i++) ra[i]     = sA[buf][k][ty * 4 + i];
            #pragma unroll
            for (int i = 0; i < 4; i++) ra[4 + i] = sA[buf][k][64 + ty * 4 + i];
            #pragma unroll
            for (int j = 0; j < 4; j++) rb[j]     = sB[buf][k][tx * 4 + j];
            #pragma unroll
            for (int i = 0; i < 8; i++)
                #pragma unroll
                for (int j = 0; j < 4; j++)
                    acc[i][j] = fmaf(ra[i], rb[j], acc[i][j]);
        }

        if (kt + 1 < NT) {
            store_tile(1 - buf);
            __syncthreads();
        }
    }

    float4 bv = *(const float4*)(bias + bn + tx * 4);
    #pragma unroll
    for (int i = 0; i < 8; i++) {
        int row = (i < 4) ? (ty * 4 + i) : (64 + ty * 4 + (i - 4));
        float4 o;
        o.x = acc[i][0] + bv.x;
        o.y = acc[i][1] + bv.y;
        o.z = acc[i][2] + bv.z;
        o.w = acc[i][3] + bv.w;
        *(float4*)(C + (size_t)(bm + row) * 256 + bn + tx * 4) = o;
    }
}

// ---------------- launch ----------------
extern "C" void kernel_launch(void* const* d_in, const int* in_sizes, int n_in,
                              void* d_out, int out_size) {
    const float* instf  = (const float*)d_in[0];
    const float* anchor = (const float*)d_in[1];
    const float* proj   = (const float*)d_in[2];
    const float* f0     = (const float*)d_in[3];
    const float* f1     = (const float*)d_in[4];
    const float* f2     = (const float*)d_in[5];
    const float* f3     = (const float*)d_in[6];
    const float* attn_w = (const float*)d_in[7];
    const float* attn_b = (const float*)d_in[8];
    const float* vp_w   = (const float*)d_in[9];
    const float* vp_b   = (const float*)d_in[10];
    const float* op_w   = (const float*)d_in[11];
    const float* op_b   = (const float*)d_in[12];
    float* out = (float*)d_out;

    // 1) transpose features to channel-last fp16 (exact grid per level)
    dim3 tb(32, 8);
    transpose_kernel<0><<<dim3(352, 8, B * CAMS), tb>>>(f0);   // 64x176
    transpose_kernel<1><<<dim3(88,  8, B * CAMS), tb>>>(f1);   // 32x88
    transpose_kernel<2><<<dim3(22,  8, B * CAMS), tb>>>(f2);   // 16x44
    transpose_kernel<3><<<dim3(6,   8, B * CAMS), tb>>>(f3);   // 8x22

    // 2) attn softmax + uv
    prep_kernel<<<(BN_PTS * 32 + 255) / 256, 256>>>(instf, anchor, proj, attn_w, attn_b);

    // 3) aggregate (8 points / block)
    aggregate_kernel<<<BN_PTS / 8, 256>>>();

    // 4) two GEMMs (R4 design)
    dim3 gg(BN_PTS / GBM, 256 / GBN);
    gemm_nt_kernel<<<gg, 256>>>(0, vp_w, vp_b, nullptr, out);
    gemm_nt_kernel<<<gg, 256>>>(1, op_w, op_b, instf, out);
}

// round 7
// speedup vs baseline: 1.8479x; 1.4955x over previous
#include <cuda_runtime.h>
#include <cuda_fp16.h>
#include <cstdint>

// ---------------- problem constants ----------------
constexpr int B    = 2;
constexpr int N    = 6400;
constexpr int E    = 256;
constexpr int CAMS = 6;
constexpr int LVLS = 4;
constexpr int BN_PTS = B * N;          // 12800
__device__ constexpr int HGT[LVLS]  = {64, 32, 16, 8};
__device__ constexpr int WID[LVLS]  = {176, 88, 44, 22};
__device__ constexpr int LOFF[LVLS] = {0, 11264, 14080, 14784};
constexpr int TOTHW = 14960;           // sum of H*W

// ---------------- device scratch (no runtime alloc allowed) ----------------
__device__ __half g_featT[(size_t)B * CAMS * TOTHW * E];  // ~92 MB, [b,c,hw,E] fp16
__device__ float  g_attn[BN_PTS * CAMS * LVLS];
__device__ float  g_uv[BN_PTS * CAMS * 2];
__device__ __half g_aggH[(size_t)BN_PTS * E];             // aggregation (fp16)
__device__ __half g_xh[(size_t)BN_PTS * E];               // after vp GEMM + residual
__device__ __half g_vpH[E * E];
__device__ __half g_opH[E * E];

// ---------------- helpers ----------------
__device__ __forceinline__ uint32_t smem_u32(const void* p) {
    return (uint32_t)__cvta_generic_to_shared(p);
}
__device__ __forceinline__ void ldmx4(unsigned r[4], uint32_t addr) {
    asm volatile("ldmatrix.sync.aligned.m8n8.x4.shared.b16 {%0,%1,%2,%3}, [%4];"
                 : "=r"(r[0]), "=r"(r[1]), "=r"(r[2]), "=r"(r[3]) : "r"(addr));
}
__device__ __forceinline__ void mma16816(float d[4], const unsigned a[4], const unsigned b[2]) {
    asm volatile("mma.sync.aligned.m16n8k16.row.col.f32.f16.f16.f32 "
                 "{%0,%1,%2,%3}, {%4,%5,%6,%7}, {%8,%9}, {%0,%1,%2,%3};"
                 : "+f"(d[0]), "+f"(d[1]), "+f"(d[2]), "+f"(d[3])
                 : "r"(a[0]), "r"(a[1]), "r"(a[2]), "r"(a[3]), "r"(b[0]), "r"(b[1]));
}

// ---------------- 0) weight fp32 -> fp16 ----------------
__global__ __launch_bounds__(256) void convert_w_kernel(const float* __restrict__ vp,
                                                        const float* __restrict__ op) {
    int i = blockIdx.x * 256 + threadIdx.x;    // 65536 threads
    g_vpH[i] = __float2half(vp[i]);
    g_opH[i] = __float2half(op[i]);
}

// ---------------- 1) feature transpose: [b,c,E,H,W] -> [b,c,HW,E] fp16 -----
template <int L>
__global__ __launch_bounds__(256) void transpose_kernel(const float* __restrict__ src0) {
    constexpr int H  = (L == 0 ? 64 : L == 1 ? 32 : L == 2 ? 16 : 8);
    constexpr int W  = (L == 0 ? 176 : L == 1 ? 88 : L == 2 ? 44 : 22);
    constexpr int HW = H * W;
    constexpr int OFF = (L == 0 ? 0 : L == 1 ? 11264 : L == 2 ? 14080 : 14784);

    int bc  = blockIdx.z;
    int hw0 = blockIdx.x * 32;
    int e0  = blockIdx.y * 32;

    const float* src = src0 + (size_t)bc * E * HW;
    __half* dst = g_featT + ((size_t)bc * TOTHW + OFF) * E;

    __shared__ float tile[32][33];        // [e][hw]
    int tx = threadIdx.x, ty = threadIdx.y;   // (32,8)
    #pragma unroll
    for (int i = 0; i < 4; i++) {
        int e  = e0 + ty + i * 8;
        int hw = hw0 + tx;
        tile[ty + i * 8][tx] = (hw < HW) ? src[(size_t)e * HW + hw] : 0.0f;
    }
    __syncthreads();
    int t   = ty * 32 + tx;
    int row = t >> 3;
    int seg = t & 7;
    int hw  = hw0 + row;
    if (hw < HW) {
        __half2 v0 = __floats2half2_rn(tile[seg * 4 + 0][row], tile[seg * 4 + 1][row]);
        __half2 v1 = __floats2half2_rn(tile[seg * 4 + 2][row], tile[seg * 4 + 3][row]);
        uint2 pk;
        pk.x = *(const unsigned*)&v0;
        pk.y = *(const unsigned*)&v1;
        *(uint2*)(dst + (size_t)hw * E + e0 + seg * 4) = pk;
    }
}

// ---------------- 2) prep: attn softmax + uv projection --------------------
__global__ __launch_bounds__(256) void prep_kernel(
                            const float* __restrict__ instf,
                            const float* __restrict__ anchor,
                            const float* __restrict__ proj,
                            const float* __restrict__ attn_w,
                            const float* __restrict__ attn_b) {
    int warp = (blockIdx.x * blockDim.x + threadIdx.x) >> 5;
    int lane = threadIdx.x & 31;
    if (warp >= BN_PTS) return;
    int p = warp;
    int b = p / N;

    const float* ifp = instf + (size_t)p * E;
    float v[8];
    #pragma unroll
    for (int k = 0; k < 8; k++) v[k] = ifp[k * 32 + lane];

    float logit[24];
    #pragma unroll
    for (int cl = 0; cl < 24; cl++) {
        const float* w = attn_w + cl * E;
        float s = 0.f;
        #pragma unroll
        for (int k = 0; k < 8; k++) s = fmaf(v[k], w[k * 32 + lane], s);
        #pragma unroll
        for (int o = 16; o; o >>= 1) s += __shfl_xor_sync(0xffffffffu, s, o);
        logit[cl] = s + attn_b[cl];
    }

    if (lane == 0) {
        #pragma unroll
        for (int c = 0; c < CAMS; c++) {
            float l0 = logit[c * 4 + 0], l1 = logit[c * 4 + 1];
            float l2 = logit[c * 4 + 2], l3 = logit[c * 4 + 3];
            float mx = fmaxf(fmaxf(l0, l1), fmaxf(l2, l3));
            float e0 = expf(l0 - mx), e1 = expf(l1 - mx);
            float e2 = expf(l2 - mx), e3 = expf(l3 - mx);
            float inv = 1.0f / (e0 + e1 + e2 + e3);
            float* ap = g_attn + (size_t)p * 24 + c * 4;
            ap[0] = e0 * inv; ap[1] = e1 * inv; ap[2] = e2 * inv; ap[3] = e3 * inv;
        }
    }

    float ax = anchor[(size_t)p * 11 + 0];
    float ay = anchor[(size_t)p * 11 + 1];
    float az = anchor[(size_t)p * 11 + 2];
    float sx = 1.0f / (1.0f + expf(-ax));
    float sy = 1.0f / (1.0f + expf(-ay));
    float sz = 1.0f / (1.0f + expf(-az));
    float X = sx * 102.4f - 51.2f;
    float Y = sy * 102.4f - 51.2f;
    float Z = sz * 8.0f   - 5.0f;

    if (lane < CAMS) {
        const float* P = proj + ((size_t)b * CAMS + lane) * 16;
        float c0 = P[0]  * X + P[1]  * Y + P[2]  * Z + P[3];
        float c1 = P[4]  * X + P[5]  * Y + P[6]  * Z + P[7];
        float c2 = P[8]  * X + P[9]  * Y + P[10] * Z + P[11];
        float d  = fmaxf(c2, 0.0001f);
        g_uv[(size_t)p * 12 + lane * 2 + 0] = c0 / d;
        g_uv[(size_t)p * 12 + lane * 2 + 1] = c1 / d;
    }
}

// ---------------- 3) bilinear gather + weighted aggregation (fp16) ---------
__global__ __launch_bounds__(256) void aggregate_kernel() {
    int t    = threadIdx.x;
    int pt   = t >> 5;
    int lane = t & 31;
    int p    = blockIdx.x * 8 + pt;
    int b    = p / N;

    __shared__ float s_attn[8][24];
    __shared__ float s_uv[8][12];
    if (lane < 24) s_attn[pt][lane] = g_attn[(size_t)p * 24 + lane];
    if (lane < 12) s_uv[pt][lane]   = g_uv[(size_t)p * 12 + lane];
    __syncthreads();

    float acc[8] = {0.f, 0.f, 0.f, 0.f, 0.f, 0.f, 0.f, 0.f};

    #pragma unroll
    for (int c = 0; c < CAMS; c++) {
        float x = s_uv[pt][c * 2 + 0];
        float y = s_uv[pt][c * 2 + 1];
        float x0 = floorf(x), y0 = floorf(y);
        float wx1 = x - x0, wx0 = 1.0f - wx1;
        float wy1 = y - y0, wy0 = 1.0f - wy1;
        const __half* base = g_featT + ((size_t)b * CAMS + c) * TOTHW * E;
        #pragma unroll
        for (int l = 0; l < LVLS; l++) {
            const int Wl = WID[l], Hl = HGT[l], off = LOFF[l];
            float wa = s_attn[pt][c * 4 + l];
            #pragma unroll
            for (int cy = 0; cy < 2; cy++) {
                float yf = y0 + cy;
                float wy = cy ? wy1 : wy0;
                if (yf < 0.f || yf > (float)(Hl - 1)) continue;
                #pragma unroll
                for (int cx = 0; cx < 2; cx++) {
                    float xf = x0 + cx;
                    float wx = cx ? wx1 : wx0;
                    if (xf < 0.f || xf > (float)(Wl - 1)) continue;
                    float wgt = wa * wx * wy;
                    int xi = (int)xf, yi = (int)yf;
                    const __half* fp = base + ((size_t)(off + yi * Wl + xi)) * E + lane * 8;
                    uint4 raw = *(const uint4*)fp;
                    const __half2* h2 = (const __half2*)&raw;
                    #pragma unroll
                    for (int q = 0; q < 4; q++) {
                        float2 f = __half22float2(h2[q]);
                        acc[q * 2 + 0] = fmaf(wgt, f.x, acc[q * 2 + 0]);
                        acc[q * 2 + 1] = fmaf(wgt, f.y, acc[q * 2 + 1]);
                    }
                }
            }
        }
    }
    // store fp16
    __half2 o0 = __floats2half2_rn(acc[0], acc[1]);
    __half2 o1 = __floats2half2_rn(acc[2], acc[3]);
    __half2 o2 = __floats2half2_rn(acc[4], acc[5]);
    __half2 o3 = __floats2half2_rn(acc[6], acc[7]);
    uint4 pk;
    pk.x = *(const unsigned*)&o0; pk.y = *(const unsigned*)&o1;
    pk.z = *(const unsigned*)&o2; pk.w = *(const unsigned*)&o3;
    *(uint4*)(g_aggH + (size_t)p * E + lane * 8) = pk;
}

// ---------------- 4) fp16 tensor-core NT-GEMM --------------------------------
// C[M,256] = A[M,256] @ W[256,256]^T (+ epilogue)
// MODE 0: A=g_aggH, W=g_vpH,  out = half(acc + vp_b[n] + instf[m][n]) -> g_xh
// MODE 1: A=g_xh,   W=g_opH,  out = float(acc + op_b[n])              -> Cout
// BM=128, BN=64, BK=64, 8 warps (4x2), warp tile 32x32, ldmatrix + mma16816.
template <int MODE>
__global__ __launch_bounds__(256) void gemm_h_kernel(
        const float* __restrict__ bias,
        const float* __restrict__ instf,
        float* __restrict__ Cout) {
    constexpr int K = 256;
    const __half* A = (MODE == 0) ? g_aggH : g_xh;
    const __half* W = (MODE == 0) ? g_vpH  : g_opH;

    __shared__ __half sA[128 * 64];
    __shared__ __half sB[64 * 64];

    int bm = blockIdx.x * 128;
    int bn = blockIdx.y * 64;
    int t  = threadIdx.x;
    int warp = t >> 5, lane = t & 31;
    int wm = warp >> 1, wn = warp & 1;      // 4 x 2 warp grid

    // swizzled smem offset (halves): row-major rows of 64 halves, 8 chunks of 8
    auto swz = [](int row, int chunk) { return row * 64 + ((chunk ^ (row & 7)) << 3); };

    float acc[2][4][4];
    #pragma unroll
    for (int i = 0; i < 2; i++)
        #pragma unroll
        for (int j = 0; j < 4; j++)
            #pragma unroll
            for (int q = 0; q < 4; q++) acc[i][j][q] = 0.f;

    int lidx = lane & 7, lg = lane >> 3;

    for (int k0 = 0; k0 < K; k0 += 64) {
        // ---- load A tile: 128 rows x 64 halves = 1024 uint4-chunks, 4/thread
        #pragma unroll
        for (int i = 0; i < 4; i++) {
            int cchunk = t + i * 256;
            int row = cchunk >> 3, ch = cchunk & 7;
            uint4 v = *(const uint4*)(A + (size_t)(bm + row) * K + k0 + ch * 8);
            *(uint4*)(sA + swz(row, ch)) = v;
        }
        // ---- load B tile: 64 rows x 64 halves = 512 chunks, 2/thread
        #pragma unroll
        for (int i = 0; i < 2; i++) {
            int cchunk = t + i * 256;
            int row = cchunk >> 3, ch = cchunk & 7;
            uint4 v = *(const uint4*)(W + (size_t)(bn + row) * K + k0 + ch * 8);
            *(uint4*)(sB + swz(row, ch)) = v;
        }
        __syncthreads();

        #pragma unroll
        for (int ks = 0; ks < 4; ks++) {     // k16 steps within BK=64
            int kc = ks * 2;                 // chunk base
            unsigned af[2][4], bf[2][4];
            // A frags: mt 0/1 ; groups: row = base + (g&1)*8 + lidx, chunk = kc + (g>>1)
            #pragma unroll
            for (int mt = 0; mt < 2; mt++) {
                int row = wm * 32 + mt * 16 + (lg & 1) * 8 + lidx;
                int ch  = kc + (lg >> 1);
                ldmx4(af[mt], smem_u32(sA + swz(row, ch)));
            }
            // B frags: 2 x ldmx4, each covers 2 n-tiles
            // groups: row = nb + ((g>>1)&1)*8 + lidx, chunk = kc + (g&1)
            #pragma unroll
            for (int h = 0; h < 2; h++) {
                int row = wn * 32 + h * 16 + ((lg >> 1) & 1) * 8 + lidx;
                int ch  = kc + (lg & 1);
                ldmx4(bf[h], smem_u32(sB + swz(row, ch)));
            }
            #pragma unroll
            for (int mt = 0; mt < 2; mt++)
                #pragma unroll
                for (int nt = 0; nt < 4; nt++)
                    mma16816(acc[mt][nt], af[mt], bf[nt >> 1] + (nt & 1) * 2);
        }
        __syncthreads();
    }

    // ---- epilogue ----
    int rbase = bm + wm * 32 + (lane >> 2);
    int cbase = bn + wn * 32 + (lane & 3) * 2;
    #pragma unroll
    for (int mt = 0; mt < 2; mt++) {
        #pragma unroll
        for (int nt = 0; nt < 4; nt++) {
            int col = cbase + nt * 8;
            float b0 = bias[col], b1 = bias[col + 1];
            #pragma unroll
            for (int h = 0; h < 2; h++) {       // row, row+8
                int row = rbase + mt * 16 + h * 8;
                float v0 = acc[mt][nt][h * 2 + 0] + b0;
                float v1 = acc[mt][nt][h * 2 + 1] + b1;
                if (MODE == 0) {
                    v0 += instf[(size_t)row * 256 + col];
                    v1 += instf[(size_t)row * 256 + col + 1];
                    __half2 hv = __floats2half2_rn(v0, v1);
                    *(__half2*)(g_xh + (size_t)row * 256 + col) = hv;
                } else {
                    *(float2*)(Cout + (size_t)row * 256 + col) = make_float2(v0, v1);
                }
            }
        }
    }
}

// ---------------- launch ----------------
extern "C" void kernel_launch(void* const* d_in, const int* in_sizes, int n_in,
                              void* d_out, int out_size) {
    const float* instf  = (const float*)d_in[0];
    const float* anchor = (const float*)d_in[1];
    const float* proj   = (const float*)d_in[2];
    const float* f0     = (const float*)d_in[3];
    const float* f1     = (const float*)d_in[4];
    const float* f2     = (const float*)d_in[5];
    const float* f3     = (const float*)d_in[6];
    const float* attn_w = (const float*)d_in[7];
    const float* attn_b = (const float*)d_in[8];
    const float* vp_w   = (const float*)d_in[9];
    const float* vp_b   = (const float*)d_in[10];
    const float* op_w   = (const float*)d_in[11];
    const float* op_b   = (const float*)d_in[12];
    float* out = (float*)d_out;

    convert_w_kernel<<<256, 256>>>(vp_w, op_w);

    dim3 tb(32, 8);
    transpose_kernel<0><<<dim3(352, 8, B * CAMS), tb>>>(f0);
    transpose_kernel<1><<<dim3(88,  8, B * CAMS), tb>>>(f1);
    transpose_kernel<2><<<dim3(22,  8, B * CAMS), tb>>>(f2);
    transpose_kernel<3><<<dim3(6,   8, B * CAMS), tb>>>(f3);

    prep_kernel<<<(BN_PTS * 32 + 255) / 256, 256>>>(instf, anchor, proj, attn_w, attn_b);

    aggregate_kernel<<<BN_PTS / 8, 256>>>();

    dim3 gg(BN_PTS / 128, 256 / 64);
    gemm_h_kernel<0><<<gg, 256>>>(vp_b, instf, out);
    gemm_h_kernel<1><<<gg, 256>>>(op_b, nullptr, out);
}

// round 8
// speedup vs baseline: 1.9702x; 1.0662x over previous
#include <cuda_runtime.h>
#include <cuda_fp16.h>
#include <cstdint>

// ---------------- problem constants ----------------
constexpr int B    = 2;
constexpr int N    = 6400;
constexpr int E    = 256;
constexpr int CAMS = 6;
constexpr int LVLS = 4;
constexpr int BN_PTS = B * N;          // 12800
__device__ constexpr int HGT[LVLS]  = {64, 32, 16, 8};
__device__ constexpr int WID[LVLS]  = {176, 88, 44, 22};
__device__ constexpr int LOFF[LVLS] = {0, 11264, 14080, 14784};
constexpr int TOTHW = 14960;           // sum of H*W

// ---------------- device scratch (no runtime alloc allowed) ----------------
__device__ __half g_featT[(size_t)B * CAMS * TOTHW * E];  // ~92 MB, [b,c,hw,E] fp16
__device__ __half g_aggH[(size_t)BN_PTS * E];             // aggregation (fp16)
__device__ __half g_xh[(size_t)BN_PTS * E];               // after vp GEMM + residual
__device__ __half g_vpH[E * E];
__device__ __half g_opH[E * E];

// ---------------- helpers ----------------
__device__ __forceinline__ uint32_t smem_u32(const void* p) {
    return (uint32_t)__cvta_generic_to_shared(p);
}
__device__ __forceinline__ void ldmx4(unsigned r[4], uint32_t addr) {
    asm volatile("ldmatrix.sync.aligned.m8n8.x4.shared.b16 {%0,%1,%2,%3}, [%4];"
                 : "=r"(r[0]), "=r"(r[1]), "=r"(r[2]), "=r"(r[3]) : "r"(addr));
}
__device__ __forceinline__ void mma16816(float d[4], const unsigned a[4], const unsigned b[2]) {
    asm volatile("mma.sync.aligned.m16n8k16.row.col.f32.f16.f16.f32 "
                 "{%0,%1,%2,%3}, {%4,%5,%6,%7}, {%8,%9}, {%0,%1,%2,%3};"
                 : "+f"(d[0]), "+f"(d[1]), "+f"(d[2]), "+f"(d[3])
                 : "r"(a[0]), "r"(a[1]), "r"(a[2]), "r"(a[3]), "r"(b[0]), "r"(b[1]));
}

// ---------------- 0) weight fp32 -> fp16 ----------------
__global__ __launch_bounds__(256) void convert_w_kernel(const float* __restrict__ vp,
                                                        const float* __restrict__ op) {
    int i = blockIdx.x * 256 + threadIdx.x;    // 65536 threads
    g_vpH[i] = __float2half(vp[i]);
    g_opH[i] = __float2half(op[i]);
}

// ---------------- 1) feature transpose: [b,c,E,HW] -> [b,c,HW,E] fp16 ------
// 64x64 tiles over flattened HW; float4 reads, uint4 (16B fp16) writes.
template <int L>
__global__ __launch_bounds__(256) void transpose_kernel(const float* __restrict__ src0) {
    constexpr int H  = (L == 0 ? 64 : L == 1 ? 32 : L == 2 ? 16 : 8);
    constexpr int W  = (L == 0 ? 176 : L == 1 ? 88 : L == 2 ? 44 : 22);
    constexpr int HW = H * W;
    constexpr int OFF = (L == 0 ? 0 : L == 1 ? 11264 : L == 2 ? 14080 : 14784);

    int bc  = blockIdx.z;                 // 0..11
    int hw0 = blockIdx.x * 64;
    int e0  = blockIdx.y * 64;
    int t   = threadIdx.x;

    const float* src = src0 + (size_t)bc * E * HW;
    __half* dst = g_featT + ((size_t)bc * TOTHW + OFF) * E;

    __shared__ float tile[64][65];        // [e][hw]

    #pragma unroll
    for (int i = 0; i < 4; i++) {
        int idx = t + i * 256;            // 0..1023
        int er  = idx >> 4;               // e row 0..63
        int c4  = idx & 15;               // float4 col
        int hw  = hw0 + c4 * 4;
        if (hw < HW) {
            float4 v = *(const float4*)(src + (size_t)(e0 + er) * HW + hw);
            tile[er][c4 * 4 + 0] = v.x;
            tile[er][c4 * 4 + 1] = v.y;
            tile[er][c4 * 4 + 2] = v.z;
            tile[er][c4 * 4 + 3] = v.w;
        }
    }
    __syncthreads();

    #pragma unroll
    for (int i = 0; i < 2; i++) {
        int idx = t + i * 256;            // 0..511
        int hwl = idx >> 3;               // hw row 0..63
        int seg = idx & 7;                // e segment of 8 halves
        int hw  = hw0 + hwl;
        if (hw < HW) {
            __half2 v0 = __floats2half2_rn(tile[seg * 8 + 0][hwl], tile[seg * 8 + 1][hwl]);
            __half2 v1 = __floats2half2_rn(tile[seg * 8 + 2][hwl], tile[seg * 8 + 3][hwl]);
            __half2 v2 = __floats2half2_rn(tile[seg * 8 + 4][hwl], tile[seg * 8 + 5][hwl]);
            __half2 v3 = __floats2half2_rn(tile[seg * 8 + 6][hwl], tile[seg * 8 + 7][hwl]);
            uint4 pk;
            pk.x = *(const unsigned*)&v0;
            pk.y = *(const unsigned*)&v1;
            pk.z = *(const unsigned*)&v2;
            pk.w = *(const unsigned*)&v3;
            *(uint4*)(dst + (size_t)hw * E + e0 + seg * 8) = pk;
        }
    }
}

// ---------------- 2+3) fused prep + bilinear gather/aggregate --------------
// 8 points per block, one warp per point. Warp computes attn softmax + uv
// into its private smem slice, then gathers fp16 features (8 ch/lane).
__global__ __launch_bounds__(256) void aggregate_kernel(
                            const float* __restrict__ instf,
                            const float* __restrict__ anchor,
                            const float* __restrict__ proj,
                            const float* __restrict__ attn_w,
                            const float* __restrict__ attn_b) {
    int t    = threadIdx.x;
    int pt   = t >> 5;                // warp / point-within-block
    int lane = t & 31;
    int p    = blockIdx.x * 8 + pt;
    int b    = p / N;

    __shared__ float s_attn[8][24];
    __shared__ float s_uv[8][14];

    // ---- prep phase (per warp) ----
    {
        const float* ifp = instf + (size_t)p * E;
        float v[8];
        #pragma unroll
        for (int k = 0; k < 8; k++) v[k] = ifp[k * 32 + lane];

        float logit[24];
        #pragma unroll
        for (int cl = 0; cl < 24; cl++) {
            const float* w = attn_w + cl * E;
            float s = 0.f;
            #pragma unroll
            for (int k = 0; k < 8; k++) s = fmaf(v[k], w[k * 32 + lane], s);
            #pragma unroll
            for (int o = 16; o; o >>= 1) s += __shfl_xor_sync(0xffffffffu, s, o);
            logit[cl] = s + attn_b[cl];
        }

        if (lane == 0) {
            #pragma unroll
            for (int c = 0; c < CAMS; c++) {
                float l0 = logit[c * 4 + 0], l1 = logit[c * 4 + 1];
                float l2 = logit[c * 4 + 2], l3 = logit[c * 4 + 3];
                float mx = fmaxf(fmaxf(l0, l1), fmaxf(l2, l3));
                float e0 = expf(l0 - mx), e1 = expf(l1 - mx);
                float e2 = expf(l2 - mx), e3 = expf(l3 - mx);
                float inv = 1.0f / (e0 + e1 + e2 + e3);
                s_attn[pt][c * 4 + 0] = e0 * inv;
                s_attn[pt][c * 4 + 1] = e1 * inv;
                s_attn[pt][c * 4 + 2] = e2 * inv;
                s_attn[pt][c * 4 + 3] = e3 * inv;
            }
        }

        float ax = anchor[(size_t)p * 11 + 0];
        float ay = anchor[(size_t)p * 11 + 1];
        float az = anchor[(size_t)p * 11 + 2];
        float sx = 1.0f / (1.0f + expf(-ax));
        float sy = 1.0f / (1.0f + expf(-ay));
        float sz = 1.0f / (1.0f + expf(-az));
        float X = sx * 102.4f - 51.2f;
        float Y = sy * 102.4f - 51.2f;
        float Z = sz * 8.0f   - 5.0f;

        if (lane < CAMS) {
            const float* P = proj + ((size_t)b * CAMS + lane) * 16;
            float c0 = P[0]  * X + P[1]  * Y + P[2]  * Z + P[3];
            float c1 = P[4]  * X + P[5]  * Y + P[6]  * Z + P[7];
            float c2 = P[8]  * X + P[9]  * Y + P[10] * Z + P[11];
            float d  = fmaxf(c2, 0.0001f);
            s_uv[pt][lane * 2 + 0] = c0 / d;
            s_uv[pt][lane * 2 + 1] = c1 / d;
        }
        __syncwarp();
    }

    // ---- gather/aggregate phase ----
    float acc[8] = {0.f, 0.f, 0.f, 0.f, 0.f, 0.f, 0.f, 0.f};

    #pragma unroll
    for (int c = 0; c < CAMS; c++) {
        float x = s_uv[pt][c * 2 + 0];
        float y = s_uv[pt][c * 2 + 1];
        float x0 = floorf(x), y0 = floorf(y);
        float wx1 = x - x0, wx0 = 1.0f - wx1;
        float wy1 = y - y0, wy0 = 1.0f - wy1;
        const __half* base = g_featT + ((size_t)b * CAMS + c) * TOTHW * E;
        #pragma unroll
        for (int l = 0; l < LVLS; l++) {
            const int Wl = WID[l], Hl = HGT[l], off = LOFF[l];
            float wa = s_attn[pt][c * 4 + l];
            #pragma unroll
            for (int cy = 0; cy < 2; cy++) {
                float yf = y0 + cy;
                float wy = cy ? wy1 : wy0;
                if (yf < 0.f || yf > (float)(Hl - 1)) continue;
                #pragma unroll
                for (int cx = 0; cx < 2; cx++) {
                    float xf = x0 + cx;
                    float wx = cx ? wx1 : wx0;
                    if (xf < 0.f || xf > (float)(Wl - 1)) continue;
                    float wgt = wa * wx * wy;
                    int xi = (int)xf, yi = (int)yf;
                    const __half* fp = base + ((size_t)(off + yi * Wl + xi)) * E + lane * 8;
                    uint4 raw = *(const uint4*)fp;
                    const __half2* h2 = (const __half2*)&raw;
                    #pragma unroll
                    for (int q = 0; q < 4; q++) {
                        float2 f = __half22float2(h2[q]);
                        acc[q * 2 + 0] = fmaf(wgt, f.x, acc[q * 2 + 0]);
                        acc[q * 2 + 1] = fmaf(wgt, f.y, acc[q * 2 + 1]);
                    }
                }
            }
        }
    }
    __half2 o0 = __floats2half2_rn(acc[0], acc[1]);
    __half2 o1 = __floats2half2_rn(acc[2], acc[3]);
    __half2 o2 = __floats2half2_rn(acc[4], acc[5]);
    __half2 o3 = __floats2half2_rn(acc[6], acc[7]);
    uint4 pk;
    pk.x = *(const unsigned*)&o0; pk.y = *(const unsigned*)&o1;
    pk.z = *(const unsigned*)&o2; pk.w = *(const unsigned*)&o3;
    *(uint4*)(g_aggH + (size_t)p * E + lane * 8) = pk;
}

// ---------------- 4) fp16 tensor-core NT-GEMM --------------------------------
// MODE 0: A=g_aggH, W=g_vpH,  out = half(acc + vp_b[n] + instf[m][n]) -> g_xh
// MODE 1: A=g_xh,   W=g_opH,  out = float(acc + op_b[n])              -> Cout
template <int MODE>
__global__ __launch_bounds__(256) void gemm_h_kernel(
        const float* __restrict__ bias,
        const float* __restrict__ instf,
        float* __restrict__ Cout) {
    constexpr int K = 256;
    const __half* A = (MODE == 0) ? g_aggH : g_xh;
    const __half* W = (MODE == 0) ? g_vpH  : g_opH;

    __shared__ __half sA[128 * 64];
    __shared__ __half sB[64 * 64];

    int bm = blockIdx.x * 128;
    int bn = blockIdx.y * 64;
    int t  = threadIdx.x;
    int warp = t >> 5, lane = t & 31;
    int wm = warp >> 1, wn = warp & 1;

    auto swz = [](int row, int chunk) { return row * 64 + ((chunk ^ (row & 7)) << 3); };

    float acc[2][4][4];
    #pragma unroll
    for (int i = 0; i < 2; i++)
        #pragma unroll
        for (int j = 0; j < 4; j++)
            #pragma unroll
            for (int q = 0; q < 4; q++) acc[i][j][q] = 0.f;

    int lidx = lane & 7, lg = lane >> 3;

    for (int k0 = 0; k0 < K; k0 += 64) {
        #pragma unroll
        for (int i = 0; i < 4; i++) {
            int cchunk = t + i * 256;
            int row = cchunk >> 3, ch = cchunk & 7;
            uint4 v = *(const uint4*)(A + (size_t)(bm + row) * K + k0 + ch * 8);
            *(uint4*)(sA + swz(row, ch)) = v;
        }
        #pragma unroll
        for (int i = 0; i < 2; i++) {
            int cchunk = t + i * 256;
            int row = cchunk >> 3, ch = cchunk & 7;
            uint4 v = *(const uint4*)(W + (size_t)(bn + row) * K + k0 + ch * 8);
            *(uint4*)(sB + swz(row, ch)) = v;
        }
        __syncthreads();

        #pragma unroll
        for (int ks = 0; ks < 4; ks++) {
            int kc = ks * 2;
            unsigned af[2][4], bf[2][4];
            #pragma unroll
            for (int mt = 0; mt < 2; mt++) {
                int row = wm * 32 + mt * 16 + (lg & 1) * 8 + lidx;
                int ch  = kc + (lg >> 1);
                ldmx4(af[mt], smem_u32(sA + swz(row, ch)));
            }
            #pragma unroll
            for (int h = 0; h < 2; h++) {
                int row = wn * 32 + h * 16 + ((lg >> 1) & 1) * 8 + lidx;
                int ch  = kc + (lg & 1);
                ldmx4(bf[h], smem_u32(sB + swz(row, ch)));
            }
            #pragma unroll
            for (int mt = 0; mt < 2; mt++)
                #pragma unroll
                for (int nt = 0; nt < 4; nt++)
                    mma16816(acc[mt][nt], af[mt], bf[nt >> 1] + (nt & 1) * 2);
        }
        __syncthreads();
    }

    int rbase = bm + wm * 32 + (lane >> 2);
    int cbase = bn + wn * 32 + (lane & 3) * 2;
    #pragma unroll
    for (int mt = 0; mt < 2; mt++) {
        #pragma unroll
        for (int nt = 0; nt < 4; nt++) {
            int col = cbase + nt * 8;
            float b0 = bias[col], b1 = bias[col + 1];
            #pragma unroll
            for (int h = 0; h < 2; h++) {
                int row = rbase + mt * 16 + h * 8;
                float v0 = acc[mt][nt][h * 2 + 0] + b0;
                float v1 = acc[mt][nt][h * 2 + 1] + b1;
                if (MODE == 0) {
                    v0 += instf[(size_t)row * 256 + col];
                    v1 += instf[(size_t)row * 256 + col + 1];
                    __half2 hv = __floats2half2_rn(v0, v1);
                    *(__half2*)(g_xh + (size_t)row * 256 + col) = hv;
                } else {
                    *(float2*)(Cout + (size_t)row * 256 + col) = make_float2(v0, v1);
                }
            }
        }
    }
}

// ---------------- launch ----------------
extern "C" void kernel_launch(void* const* d_in, const int* in_sizes, int n_in,
                              void* d_out, int out_size) {
    const float* instf  = (const float*)d_in[0];
    const float* anchor = (const float*)d_in[1];
    const float* proj   = (const float*)d_in[2];
    const float* f0     = (const float*)d_in[3];
    const float* f1     = (const float*)d_in[4];
    const float* f2     = (const float*)d_in[5];
    const float* f3     = (const float*)d_in[6];
    const float* attn_w = (const float*)d_in[7];
    const float* attn_b = (const float*)d_in[8];
    const float* vp_w   = (const float*)d_in[9];
    const float* vp_b   = (const float*)d_in[10];
    const float* op_w   = (const float*)d_in[11];
    const float* op_b   = (const float*)d_in[12];
    float* out = (float*)d_out;

    convert_w_kernel<<<256, 256>>>(vp_w, op_w);

    // transpose: 64x64 tiles over flattened HW
    transpose_kernel<0><<<dim3(176, 4, B * CAMS), 256>>>(f0);  // HW=11264
    transpose_kernel<1><<<dim3(44,  4, B * CAMS), 256>>>(f1);  // HW=2816
    transpose_kernel<2><<<dim3(11,  4, B * CAMS), 256>>>(f2);  // HW=704
    transpose_kernel<3><<<dim3(3,   4, B * CAMS), 256>>>(f3);  // HW=176

    // fused prep + aggregate
    aggregate_kernel<<<BN_PTS / 8, 256>>>(instf, anchor, proj, attn_w, attn_b);

    dim3 gg(BN_PTS / 128, 256 / 64);
    gemm_h_kernel<0><<<gg, 256>>>(vp_b, instf, out);
    gemm_h_kernel<1><<<gg, 256>>>(op_b, nullptr, out);
}